// round 6
// baseline (speedup 1.0000x reference)
#include <cuda_runtime.h>
#include <cstdint>

#define DD    128
#define NNB   32
#define STRW  132              // w_s stride; fragment-major + k-row permuted
#define STRA  136              // nb_s stride (8 mod 32 -> conflict-free float2 A loads)
#define LRELU_ALPHA 0.2f

// w_s : k-row d stored at smem row (d & ~7) + rho(d&7), rho(x) = (x>>1) + 4*(x&1)
//       within row: pos(e) = (e&7)*16 + (e>>3); values pre-rounded to tf32 (rna)
// virtual-k: MMA slot qc holds physical k=2qc, slot qc+4 holds 2qc+1, so the A
// fragment {slot qc, slot qc+4} is a contiguous float2 in row-major nb_s.

__device__ __forceinline__ uint32_t cvt_tf32(float f) {
    uint32_t r;
    asm("cvt.rna.tf32.f32 %0, %1;" : "=r"(r) : "f"(f));
    return r;
}
__device__ __forceinline__ float cvt_tf32f(float f) { return __uint_as_float(cvt_tf32(f)); }

__device__ __forceinline__ void mma_tf32(float& c0, float& c1, float& c2, float& c3,
                                         float a0, float a1, float a2, float a3,
                                         float b0, float b1) {
    // A passed as raw fp32 bits (HMMA truncates); B pre-rounded RNA in smem
    asm volatile(
        "mma.sync.aligned.m16n8k8.row.col.f32.tf32.tf32.f32 "
        "{%0,%1,%2,%3}, {%4,%5,%6,%7}, {%8,%9}, {%0,%1,%2,%3};"
        : "+f"(c0), "+f"(c1), "+f"(c2), "+f"(c3)
        : "r"(__float_as_uint(a0)), "r"(__float_as_uint(a1)),
          "r"(__float_as_uint(a2)), "r"(__float_as_uint(a3)),
          "r"(__float_as_uint(b0)), "r"(__float_as_uint(b1)));
}

__device__ __forceinline__ void cp_async16(uint32_t smem_addr, const void* gptr) {
    asm volatile("cp.async.cg.shared.global [%0], [%1], 16;\n"
                 :: "r"(smem_addr), "l"(gptr));
}
__device__ __forceinline__ void cp_commit() { asm volatile("cp.async.commit_group;\n" ::); }
__device__ __forceinline__ void cp_wait1()  { asm volatile("cp.async.wait_group 1;\n" ::); }

extern "C" __global__ void __launch_bounds__(256, 2)
gat_reg2(const float* __restrict__ self_v,
         const float* __restrict__ nbv,
         const float* __restrict__ w,
         const float* __restrict__ q,
         float* __restrict__ out,
         int B)
{
    extern __shared__ float sm[];
    float* w_s     = sm;                         // 128*132 = 16896
    float* nb_s    = w_s + DD * STRW;            // 2 * 32*136 = 8704
    float* self_s  = nb_s + 2 * NNB * STRA;      // 2*128
    float* q_s     = self_s + 2 * DD;            // 128
    float* scoreP  = q_s + DD;                   // 4*32
    float* alpha_s = scoreP + 4 * NNB;           // 32
    float* outP    = alpha_s + NNB;              // 2*128

    const int t    = threadIdx.x;
    const int lane = t & 31;
    const int ww   = t >> 5;
    const int qr   = lane >> 2;     // 0..7
    const int qc   = lane & 3;      // 0..3
    const int h    = ww >> 2;       // row half: rows 16h..16h+15
    const int eb   = ww & 3;        // col block: 32eb..32eb+31

    // ---- one-time: w -> fragment-major, k-permuted, tf32-rounded smem ----
    {
        const float4* wg = reinterpret_cast<const float4*>(w);
        #pragma unroll
        for (int i = 0; i < 16; ++i) {
            const int fi = t + i * 256;
            const int d  = fi >> 5, e4 = fi & 31;
            const int d8 = d & 7;
            const int dr = (d & ~7) + ((d8 >> 1) + ((d8 & 1) << 2));  // rho perm
            const float4 v = wg[fi];
            const int e0 = 4 * e4;
            w_s[dr * STRW + ((e0 + 0) & 7) * 16 + ((e0 + 0) >> 3)] = cvt_tf32f(v.x);
            w_s[dr * STRW + ((e0 + 1) & 7) * 16 + ((e0 + 1) >> 3)] = cvt_tf32f(v.y);
            w_s[dr * STRW + ((e0 + 2) & 7) * 16 + ((e0 + 2) >> 3)] = cvt_tf32f(v.z);
            w_s[dr * STRW + ((e0 + 3) & 7) * 16 + ((e0 + 3) >> 3)] = cvt_tf32f(v.w);
        }
        if (t < DD) q_s[t] = q[t];
    }

    auto issue_tile = [&](int p, int buf) {
        if (p < B) {
            const float4* src = reinterpret_cast<const float4*>(nbv + (size_t)p * NNB * DD);
            const uint32_t dst0 =
                (uint32_t)__cvta_generic_to_shared(nb_s + buf * NNB * STRA);
            #pragma unroll
            for (int i = 0; i < 4; ++i) {                 // 1024 float4 / 256 thr
                const int fi = t + i * 256;
                const int r  = fi >> 5, c4 = fi & 31;
                cp_async16(dst0 + (uint32_t)(r * STRA + 4 * c4) * 4u, src + fi);
            }
            if (t < 32) {
                const uint32_t ds =
                    (uint32_t)__cvta_generic_to_shared(self_s + buf * DD) + t * 16u;
                cp_async16(ds, reinterpret_cast<const float4*>(self_v + (size_t)p * DD) + t);
            }
        }
        cp_commit();
    };

    issue_tile(blockIdx.x, 0);
    issue_tile(blockIdx.x + gridDim.x, 1);

    int it = 0;
    for (int p = blockIdx.x; p < B; p += gridDim.x, ++it) {
        const int cur = it & 1;
        cp_wait1();
        __syncthreads();                          // tile[cur] (+ w_s on iter 0) visible

        const float* nbuf = nb_s + cur * NNB * STRA;

        // ---- MMA mainloop: warp tile = 16 rows x 32 cols, no ALU in loop ----
        float acc[4][4];
        #pragma unroll
        for (int j = 0; j < 4; ++j)
            #pragma unroll
            for (int k = 0; k < 4; ++k) acc[j][k] = 0.f;

        const float* ar0 = nbuf + (16 * h + qr) * STRA + 2 * qc;  // row 16h+qr
        const float* ar1 = ar0 + 8 * STRA;                        // row 16h+qr+8
        const float* bp  = w_s + qc * STRW + qr * 16 + 4 * eb;

        #pragma unroll
        for (int k0 = 0; k0 < DD; k0 += 8) {
            const float2 A0 = *reinterpret_cast<const float2*>(ar0 + k0); // slots qc,qc+4
            const float2 A1 = *reinterpret_cast<const float2*>(ar1 + k0);
            const float* bk = bp + k0 * STRW;
            const float4 B0 = *reinterpret_cast<const float4*>(bk);            // slot qc
            const float4 B1 = *reinterpret_cast<const float4*>(bk + 4 * STRW); // slot qc+4
            mma_tf32(acc[0][0],acc[0][1],acc[0][2],acc[0][3], A0.x,A1.x,A0.y,A1.y, B0.x,B1.x);
            mma_tf32(acc[1][0],acc[1][1],acc[1][2],acc[1][3], A0.x,A1.x,A0.y,A1.y, B0.y,B1.y);
            mma_tf32(acc[2][0],acc[2][1],acc[2][2],acc[2][3], A0.x,A1.x,A0.y,A1.y, B0.z,B1.z);
            mma_tf32(acc[3][0],acc[3][1],acc[3][2],acc[3][3], A0.x,A1.x,A0.y,A1.y, B0.w,B1.w);
        }

        // ---- score partials: rows 16h+qr / +8, this warp's 32 cols ----
        {
            const float* selfb = self_s + cur * DD;
            float p_lo = 0.f, p_hi = 0.f;
            #pragma unroll
            for (int j = 0; j < 4; ++j) {
                const int e0 = 32 * eb + 8 * j + 2 * qc;
                const float2 sv = *reinterpret_cast<const float2*>(selfb + e0);
                const float2 qv = *reinterpret_cast<const float2*>(q_s + e0);
                float v;
                v = sv.x * acc[j][0]; v = (v >= 0.f) ? v : LRELU_ALPHA * v; p_lo = fmaf(v, qv.x, p_lo);
                v = sv.y * acc[j][1]; v = (v >= 0.f) ? v : LRELU_ALPHA * v; p_lo = fmaf(v, qv.y, p_lo);
                v = sv.x * acc[j][2]; v = (v >= 0.f) ? v : LRELU_ALPHA * v; p_hi = fmaf(v, qv.x, p_hi);
                v = sv.y * acc[j][3]; v = (v >= 0.f) ? v : LRELU_ALPHA * v; p_hi = fmaf(v, qv.y, p_hi);
            }
            p_lo += __shfl_xor_sync(0xffffffffu, p_lo, 1);
            p_lo += __shfl_xor_sync(0xffffffffu, p_lo, 2);
            p_hi += __shfl_xor_sync(0xffffffffu, p_hi, 1);
            p_hi += __shfl_xor_sync(0xffffffffu, p_hi, 2);
            if (qc == 0) {
                scoreP[eb * NNB + 16 * h + qr]     = p_lo;
                scoreP[eb * NNB + 16 * h + qr + 8] = p_hi;
            }
        }
        __syncthreads();

        // ---- softmax over 32 neighbors (warp 0) ----
        if (t < NNB) {
            const float s = scoreP[t] + scoreP[NNB + t]
                          + scoreP[2 * NNB + t] + scoreP[3 * NNB + t];
            float mx = s;
            #pragma unroll
            for (int off = 16; off > 0; off >>= 1)
                mx = fmaxf(mx, __shfl_xor_sync(0xffffffffu, mx, off));
            const float ex = __expf(s - mx);
            float sum = ex;
            #pragma unroll
            for (int off = 16; off > 0; off >>= 1)
                sum += __shfl_xor_sync(0xffffffffu, sum, off);
            alpha_s[t] = ex / sum;
        }
        __syncthreads();                          // alpha ready; nb/self[cur] dead

        issue_tile(p + 2 * gridDim.x, cur);       // refill freed buffer

        // ---- register epilogue: partial out over this warp's 16 rows ----
        {
            const float al_lo = alpha_s[16 * h + qr];
            const float al_hi = alpha_s[16 * h + qr + 8];
            #pragma unroll
            for (int j = 0; j < 4; ++j)
                #pragma unroll
                for (int u = 0; u < 2; ++u) {
                    float v = al_lo * acc[j][u];
                    v = fmaf(al_hi, acc[j][2 + u], v);
                    v += __shfl_xor_sync(0xffffffffu, v, 4);
                    v += __shfl_xor_sync(0xffffffffu, v, 8);
                    v += __shfl_xor_sync(0xffffffffu, v, 16);
                    if (qr == 0)
                        outP[h * DD + 32 * eb + 8 * j + 2 * qc + u] = v;
                }
        }
        __syncthreads();

        if (t < DD)
            out[(size_t)p * DD + t] = outP[t] + outP[DD + t];
        // loop-top __syncthreads orders outP/nb reuse vs these reads
    }
}

extern "C" void kernel_launch(void* const* d_in, const int* in_sizes, int n_in,
                              void* d_out, int out_size)
{
    const float* self_v = (const float*)d_in[0];   // [B,128]
    const float* nbv    = (const float*)d_in[1];   // [B,32,128]
    const float* w      = (const float*)d_in[2];   // [128,128]
    const float* q      = (const float*)d_in[3];   // [128,1]
    float*       out    = (float*)d_out;           // [B,128]

    const int B = in_sizes[0] / DD;                // 20000

    int smc = 0;
    cudaDeviceGetAttribute(&smc, cudaDevAttrMultiProcessorCount, 0);
    if (smc <= 0) smc = 148;
    int grid = 2 * smc;
    if (grid > B) grid = B;

    const size_t smem_bytes =
        (size_t)(DD * STRW + 2 * NNB * STRA + 2 * DD + DD + 4 * NNB + NNB + 2 * DD)
        * sizeof(float);                           // 105,600 B

    cudaFuncSetAttribute(gat_reg2, cudaFuncAttributeMaxDynamicSharedMemorySize,
                         (int)smem_bytes);

    gat_reg2<<<grid, 256, smem_bytes>>>(self_v, nbv, w, q, out, B);
}

// round 7
// speedup vs baseline: 1.0473x; 1.0473x over previous
#include <cuda_runtime.h>
#include <cstdint>

#define DD    128
#define NNB   32
#define STRW  132              // w_s stride; fragment-major + k-row permuted
#define STRA  136              // nb_s stride (8 mod 32 -> conflict-free float2 A loads)
#define LRELU_ALPHA 0.2f

// w_s : k-row d stored at smem row (d & ~7) + rho(d&7), rho(x) = (x>>1) + 4*(x&1)
//       within row: pos(e) = (e&7)*16 + (e>>3); values pre-rounded to tf32 (rna)
// virtual-k: MMA slot qc = physical k 2qc, slot qc+4 = 2qc+1 -> A frag is a float2.

__device__ __forceinline__ uint32_t cvt_tf32(float f) {
    uint32_t r;
    asm("cvt.rna.tf32.f32 %0, %1;" : "=r"(r) : "f"(f));
    return r;
}
__device__ __forceinline__ float cvt_tf32f(float f) { return __uint_as_float(cvt_tf32(f)); }

__device__ __forceinline__ void mma_tf32(float& c0, float& c1, float& c2, float& c3,
                                         float a0, float a1, float a2, float a3,
                                         float b0, float b1) {
    // A raw fp32 bits (HMMA truncates); B pre-rounded RNA in smem
    asm volatile(
        "mma.sync.aligned.m16n8k8.row.col.f32.tf32.tf32.f32 "
        "{%0,%1,%2,%3}, {%4,%5,%6,%7}, {%8,%9}, {%0,%1,%2,%3};"
        : "+f"(c0), "+f"(c1), "+f"(c2), "+f"(c3)
        : "r"(__float_as_uint(a0)), "r"(__float_as_uint(a1)),
          "r"(__float_as_uint(a2)), "r"(__float_as_uint(a3)),
          "r"(__float_as_uint(b0)), "r"(__float_as_uint(b1)));
}

__device__ __forceinline__ void cp_async16(uint32_t smem_addr, const void* gptr) {
    asm volatile("cp.async.cg.shared.global [%0], [%1], 16;\n"
                 :: "r"(smem_addr), "l"(gptr));
}
__device__ __forceinline__ void cp_commit() { asm volatile("cp.async.commit_group;\n" ::); }
__device__ __forceinline__ void cp_wait1()  { asm volatile("cp.async.wait_group 1;\n" ::); }

extern "C" __global__ void __launch_bounds__(256, 2)
gat_reg3(const float* __restrict__ self_v,
         const float* __restrict__ nbv,
         const float* __restrict__ w,
         const float* __restrict__ q,
         float* __restrict__ out,
         int B)
{
    extern __shared__ float sm[];
    float* w_s     = sm;                         // 128*132 = 16896
    float* nb_s    = w_s + DD * STRW;            // 2 * 32*136 = 8704
    float* self_s  = nb_s + 2 * NNB * STRA;      // 2*128
    float* q_s     = self_s + 2 * DD;            // 128
    float* scoreP  = q_s + DD;                   // 4*32
    float* alpha_s = scoreP + 4 * NNB;           // 32

    const int t    = threadIdx.x;
    const int lane = t & 31;
    const int ww   = t >> 5;
    const int qr   = lane >> 2;     // 0..7
    const int qc   = lane & 3;      // 0..3
    const bool is_mma = (ww < 4);
    const int eb   = ww & 3;        // col block 32eb..32eb+31

    // ---- one-time: w -> fragment-major, k-permuted, tf32-rounded smem ----
    {
        const float4* wg = reinterpret_cast<const float4*>(w);
        #pragma unroll
        for (int i = 0; i < 16; ++i) {
            const int fi = t + i * 256;
            const int d  = fi >> 5, e4 = fi & 31;
            const int d8 = d & 7;
            const int dr = (d & ~7) + ((d8 >> 1) + ((d8 & 1) << 2));  // rho perm
            const float4 v = wg[fi];
            const int e0 = 4 * e4;
            w_s[dr * STRW + ((e0 + 0) & 7) * 16 + ((e0 + 0) >> 3)] = cvt_tf32f(v.x);
            w_s[dr * STRW + ((e0 + 1) & 7) * 16 + ((e0 + 1) >> 3)] = cvt_tf32f(v.y);
            w_s[dr * STRW + ((e0 + 2) & 7) * 16 + ((e0 + 2) >> 3)] = cvt_tf32f(v.z);
            w_s[dr * STRW + ((e0 + 3) & 7) * 16 + ((e0 + 3) >> 3)] = cvt_tf32f(v.w);
        }
        if (t < DD) q_s[t] = q[t];
    }

    auto issue_tile = [&](int p, int buf) {
        if (p < B) {
            const float4* src = reinterpret_cast<const float4*>(nbv + (size_t)p * NNB * DD);
            const uint32_t dst0 =
                (uint32_t)__cvta_generic_to_shared(nb_s + buf * NNB * STRA);
            #pragma unroll
            for (int i = 0; i < 4; ++i) {                 // 1024 float4 / 256 thr
                const int fi = t + i * 256;
                const int r  = fi >> 5, c4 = fi & 31;
                cp_async16(dst0 + (uint32_t)(r * STRA + 4 * c4) * 4u, src + fi);
            }
            if (t < 32) {
                const uint32_t ds =
                    (uint32_t)__cvta_generic_to_shared(self_s + buf * DD) + t * 16u;
                cp_async16(ds, reinterpret_cast<const float4*>(self_v + (size_t)p * DD) + t);
            }
        }
        cp_commit();
    };

    issue_tile(blockIdx.x, 0);
    issue_tile(blockIdx.x + gridDim.x, 1);

    int it = 0;
    for (int p = blockIdx.x; p < B; p += gridDim.x, ++it) {
        const int cur = it & 1;
        cp_wait1();
        __syncthreads();                          // tile[cur] (+ w_s on iter 0) visible

        const float* nbuf = nb_s + cur * NNB * STRA;

        float acc[2][4][4];                       // [row-tile T][col j][frag]
        if (is_mma) {
            #pragma unroll
            for (int T = 0; T < 2; ++T)
                #pragma unroll
                for (int j = 0; j < 4; ++j)
                    #pragma unroll
                    for (int k = 0; k < 4; ++k) acc[T][j][k] = 0.f;

            const float* ar = nbuf + qr * STRA + 2 * qc;
            const float* bp = w_s + qc * STRW + qr * 16 + 4 * eb;

            #pragma unroll
            for (int k0 = 0; k0 < DD; k0 += 8) {
                const float2 A0 = *reinterpret_cast<const float2*>(ar + k0);             // row qr
                const float2 A1 = *reinterpret_cast<const float2*>(ar + 8 * STRA + k0);  // qr+8
                const float2 A2 = *reinterpret_cast<const float2*>(ar + 16 * STRA + k0); // 16+qr
                const float2 A3 = *reinterpret_cast<const float2*>(ar + 24 * STRA + k0); // 24+qr
                const float* bk = bp + k0 * STRW;
                const float4 B0 = *reinterpret_cast<const float4*>(bk);            // slot qc
                const float4 B1 = *reinterpret_cast<const float4*>(bk + 4 * STRW); // slot qc+4
                mma_tf32(acc[0][0][0],acc[0][0][1],acc[0][0][2],acc[0][0][3], A0.x,A1.x,A0.y,A1.y, B0.x,B1.x);
                mma_tf32(acc[1][0][0],acc[1][0][1],acc[1][0][2],acc[1][0][3], A2.x,A3.x,A2.y,A3.y, B0.x,B1.x);
                mma_tf32(acc[0][1][0],acc[0][1][1],acc[0][1][2],acc[0][1][3], A0.x,A1.x,A0.y,A1.y, B0.y,B1.y);
                mma_tf32(acc[1][1][0],acc[1][1][1],acc[1][1][2],acc[1][1][3], A2.x,A3.x,A2.y,A3.y, B0.y,B1.y);
                mma_tf32(acc[0][2][0],acc[0][2][1],acc[0][2][2],acc[0][2][3], A0.x,A1.x,A0.y,A1.y, B0.z,B1.z);
                mma_tf32(acc[1][2][0],acc[1][2][1],acc[1][2][2],acc[1][2][3], A2.x,A3.x,A2.y,A3.y, B0.z,B1.z);
                mma_tf32(acc[0][3][0],acc[0][3][1],acc[0][3][2],acc[0][3][3], A0.x,A1.x,A0.y,A1.y, B0.w,B1.w);
                mma_tf32(acc[1][3][0],acc[1][3][1],acc[1][3][2],acc[1][3][3], A2.x,A3.x,A2.y,A3.y, B0.w,B1.w);
            }

            // ---- score partials: rows {qr,qr+8,16+qr,24+qr}, 32 cols ----
            const float* selfb = self_s + cur * DD;
            float pr[4] = {0.f, 0.f, 0.f, 0.f};
            #pragma unroll
            for (int j = 0; j < 4; ++j) {
                const int e0 = 32 * eb + 8 * j + 2 * qc;
                const float2 sv = *reinterpret_cast<const float2*>(selfb + e0);
                const float2 qv = *reinterpret_cast<const float2*>(q_s + e0);
                #pragma unroll
                for (int T = 0; T < 2; ++T) {
                    float v;
                    v = sv.x * acc[T][j][0]; v = (v >= 0.f) ? v : LRELU_ALPHA * v;
                    pr[2*T]   = fmaf(v, qv.x, pr[2*T]);
                    v = sv.y * acc[T][j][1]; v = (v >= 0.f) ? v : LRELU_ALPHA * v;
                    pr[2*T]   = fmaf(v, qv.y, pr[2*T]);
                    v = sv.x * acc[T][j][2]; v = (v >= 0.f) ? v : LRELU_ALPHA * v;
                    pr[2*T+1] = fmaf(v, qv.x, pr[2*T+1]);
                    v = sv.y * acc[T][j][3]; v = (v >= 0.f) ? v : LRELU_ALPHA * v;
                    pr[2*T+1] = fmaf(v, qv.y, pr[2*T+1]);
                }
            }
            #pragma unroll
            for (int i = 0; i < 4; ++i) {
                pr[i] += __shfl_xor_sync(0xffffffffu, pr[i], 1);
                pr[i] += __shfl_xor_sync(0xffffffffu, pr[i], 2);
            }
            if (qc == 0) {
                scoreP[eb * NNB + qr]      = pr[0];
                scoreP[eb * NNB + qr + 8]  = pr[1];
                scoreP[eb * NNB + qr + 16] = pr[2];
                scoreP[eb * NNB + qr + 24] = pr[3];
            }
        }
        __syncthreads();

        // ---- softmax over 32 neighbors (warp 0) ----
        if (t < NNB) {
            const float s = scoreP[t] + scoreP[NNB + t]
                          + scoreP[2 * NNB + t] + scoreP[3 * NNB + t];
            float mx = s;
            #pragma unroll
            for (int off = 16; off > 0; off >>= 1)
                mx = fmaxf(mx, __shfl_xor_sync(0xffffffffu, mx, off));
            const float ex = __expf(s - mx);
            float sum = ex;
            #pragma unroll
            for (int off = 16; off > 0; off >>= 1)
                sum += __shfl_xor_sync(0xffffffffu, sum, off);
            alpha_s[t] = ex / sum;
        }
        __syncthreads();                          // alpha ready; nb/self[cur] dead

        issue_tile(p + 2 * gridDim.x, cur);       // refill freed buffer

        // ---- register epilogue: out[e] = sum_n alpha[n]*msg (direct STG) ----
        if (is_mma) {
            const float al0 = alpha_s[qr];
            const float al1 = alpha_s[qr + 8];
            const float al2 = alpha_s[qr + 16];
            const float al3 = alpha_s[qr + 24];
            float val[4][2];
            #pragma unroll
            for (int j = 0; j < 4; ++j)
                #pragma unroll
                for (int u = 0; u < 2; ++u) {
                    float v = al0 * acc[0][j][u];
                    v = fmaf(al1, acc[0][j][2 + u], v);
                    v = fmaf(al2, acc[1][j][u], v);
                    v = fmaf(al3, acc[1][j][2 + u], v);
                    v += __shfl_xor_sync(0xffffffffu, v, 4);
                    v += __shfl_xor_sync(0xffffffffu, v, 8);
                    v += __shfl_xor_sync(0xffffffffu, v, 16);
                    val[j][u] = v;
                }
            if (qr == 0) {
                float* op = out + (size_t)p * DD + 32 * eb + 2 * qc;
                #pragma unroll
                for (int j = 0; j < 4; ++j) {
                    op[8 * j]     = val[j][0];
                    op[8 * j + 1] = val[j][1];
                }
            }
        }
        // loop-top __syncthreads orders next tile's smem writes vs these reads
    }
}

extern "C" void kernel_launch(void* const* d_in, const int* in_sizes, int n_in,
                              void* d_out, int out_size)
{
    const float* self_v = (const float*)d_in[0];   // [B,128]
    const float* nbv    = (const float*)d_in[1];   // [B,32,128]
    const float* w      = (const float*)d_in[2];   // [128,128]
    const float* q      = (const float*)d_in[3];   // [128,1]
    float*       out    = (float*)d_out;           // [B,128]

    const int B = in_sizes[0] / DD;                // 20000

    int smc = 0;
    cudaDeviceGetAttribute(&smc, cudaDevAttrMultiProcessorCount, 0);
    if (smc <= 0) smc = 148;
    int grid = 2 * smc;
    if (grid > B) grid = B;

    const size_t smem_bytes =
        (size_t)(DD * STRW + 2 * NNB * STRA + 2 * DD + DD + 4 * NNB + NNB)
        * sizeof(float);                           // 104,576 B

    cudaFuncSetAttribute(gat_reg3, cudaFuncAttributeMaxDynamicSharedMemorySize,
                         (int)smem_bytes);

    gat_reg3<<<grid, 256, smem_bytes>>>(self_v, nbv, w, q, out, B);
}

// round 8
// speedup vs baseline: 1.2775x; 1.2198x over previous
#include <cuda_runtime.h>
#include <cstdint>

#define DD    128
#define NNB   32
#define STRW  132              // w_s stride; fragment-major + k-row permuted
#define STRA  136              // nb_s stride (8 mod 32 -> conflict-free float2 A loads)
#define NGRP  4                // independent 128-thread groups per CTA
#define LRELU_ALPHA 0.2f

// w_s : k-row d stored at smem row (d & ~7) + rho(d&7), rho(x) = (x>>1) + 4*(x&1)
//       within row: pos(e) = (e&7)*16 + (e>>3); values pre-rounded to tf32 (rna)
// virtual-k: MMA slot qc = physical k 2qc, slot qc+4 = 2qc+1 -> A frag is a float2.

__device__ __forceinline__ uint32_t cvt_tf32(float f) {
    uint32_t r;
    asm("cvt.rna.tf32.f32 %0, %1;" : "=r"(r) : "f"(f));
    return r;
}
__device__ __forceinline__ float cvt_tf32f(float f) { return __uint_as_float(cvt_tf32(f)); }

__device__ __forceinline__ void mma_tf32(float& c0, float& c1, float& c2, float& c3,
                                         float a0, float a1, float a2, float a3,
                                         float b0, float b1) {
    asm volatile(
        "mma.sync.aligned.m16n8k8.row.col.f32.tf32.tf32.f32 "
        "{%0,%1,%2,%3}, {%4,%5,%6,%7}, {%8,%9}, {%0,%1,%2,%3};"
        : "+f"(c0), "+f"(c1), "+f"(c2), "+f"(c3)
        : "r"(__float_as_uint(a0)), "r"(__float_as_uint(a1)),
          "r"(__float_as_uint(a2)), "r"(__float_as_uint(a3)),
          "r"(__float_as_uint(b0)), "r"(__float_as_uint(b1)));
}

__device__ __forceinline__ void cp_async16(uint32_t smem_addr, const void* gptr) {
    asm volatile("cp.async.cg.shared.global [%0], [%1], 16;\n"
                 :: "r"(smem_addr), "l"(gptr));
}
__device__ __forceinline__ void cp_commit() { asm volatile("cp.async.commit_group;\n" ::); }
__device__ __forceinline__ void cp_wait1()  { asm volatile("cp.async.wait_group 1;\n" ::); }

// group-scoped barrier: named barrier id 1..4, 128 threads (4 full warps)
__device__ __forceinline__ void barg(int id) {
    asm volatile("bar.sync %0, 128;" :: "r"(id) : "memory");
}

extern "C" __global__ void __launch_bounds__(512, 1)
gat_grp(const float* __restrict__ self_v,
        const float* __restrict__ nbv,
        const float* __restrict__ w,
        const float* __restrict__ q,
        float* __restrict__ out,
        int B)
{
    extern __shared__ float sm[];
    float* w_s     = sm;                              // 128*132 = 16896 f
    float* nb_s    = w_s + DD * STRW;                 // 4 grp * 2 buf * 32*136 = 34816 f
    float* self_s  = nb_s + NGRP * 2 * NNB * STRA;    // 4*2*128 = 1024 f
    float* q_s     = self_s + NGRP * 2 * DD;          // 128 f
    float* scoreP  = q_s + DD;                        // 4*4*32 = 512 f
    float* alpha_s = scoreP + NGRP * 4 * NNB;         // 4*32 f

    const int t    = threadIdx.x;
    const int lane = t & 31;
    const int ww   = t >> 5;        // warp 0..15
    const int g    = ww >> 2;       // group 0..3
    const int eb   = ww & 3;        // warp-in-group = col block 32eb..32eb+31
    const int gt   = t & 127;       // thread-in-group
    const int qr   = lane >> 2;     // 0..7
    const int qc   = lane & 3;      // 0..3

    float* nb_g    = nb_s + g * 2 * NNB * STRA;
    float* self_g  = self_s + g * 2 * DD;
    float* scoreG  = scoreP + g * 4 * NNB;
    float* alpha_g = alpha_s + g * NNB;
    const int bid  = g + 1;         // named barrier id (avoid 0 = syncthreads)

    // ---- one-time: w -> fragment-major, k-permuted, tf32-rounded smem ----
    {
        const float4* wg = reinterpret_cast<const float4*>(w);
        #pragma unroll
        for (int i = 0; i < 8; ++i) {                 // 4096 float4 / 512 thr
            const int fi = t + i * 512;
            const int d  = fi >> 5, e4 = fi & 31;
            const int d8 = d & 7;
            const int dr = (d & ~7) + ((d8 >> 1) + ((d8 & 1) << 2));  // rho perm
            const float4 v = wg[fi];
            const int e0 = 4 * e4;
            w_s[dr * STRW + ((e0 + 0) & 7) * 16 + ((e0 + 0) >> 3)] = cvt_tf32f(v.x);
            w_s[dr * STRW + ((e0 + 1) & 7) * 16 + ((e0 + 1) >> 3)] = cvt_tf32f(v.y);
            w_s[dr * STRW + ((e0 + 2) & 7) * 16 + ((e0 + 2) >> 3)] = cvt_tf32f(v.z);
            w_s[dr * STRW + ((e0 + 3) & 7) * 16 + ((e0 + 3) >> 3)] = cvt_tf32f(v.w);
        }
        if (t < DD) q_s[t] = q[t];
    }

    const int stride = gridDim.x * NGRP;
    const int p0     = blockIdx.x * NGRP + g;

    // group-local tile prefetch (128 threads). Commit ALWAYS (keeps per-thread
    // cp.async group counts aligned with cp_wait1 bookkeeping).
    auto issue_tile = [&](int p, int buf) {
        if (p < B) {
            const float4* src = reinterpret_cast<const float4*>(nbv + (size_t)p * NNB * DD);
            const uint32_t dst0 =
                (uint32_t)__cvta_generic_to_shared(nb_g + buf * NNB * STRA);
            #pragma unroll
            for (int i = 0; i < 8; ++i) {             // 1024 float4 / 128 thr
                const int fi = gt + i * 128;
                const int r  = fi >> 5, c4 = fi & 31;
                cp_async16(dst0 + (uint32_t)(r * STRA + 4 * c4) * 4u, src + fi);
            }
            if (gt < 32) {
                const uint32_t ds =
                    (uint32_t)__cvta_generic_to_shared(self_g + buf * DD) + gt * 16u;
                cp_async16(ds, reinterpret_cast<const float4*>(self_v + (size_t)p * DD) + gt);
            }
        }
        cp_commit();
    };

    issue_tile(p0, 0);
    issue_tile(p0 + stride, 1);
    cp_wait1();                     // tile 0 landed (own-thread view)
    __syncthreads();                // w_s + cross-thread tile-0 visibility (once)

    int it = 0;
    for (int p = p0; p < B; p += stride, ++it) {
        const int cur = it & 1;
        const float* nbuf = nb_g + cur * NNB * STRA;

        // ---- MMA mainloop: warp tile = 32 rows x 32 cols, no ALU ----
        float acc[2][4][4];
        #pragma unroll
        for (int T = 0; T < 2; ++T)
            #pragma unroll
            for (int j = 0; j < 4; ++j)
                #pragma unroll
                for (int k = 0; k < 4; ++k) acc[T][j][k] = 0.f;

        const float* ar = nbuf + qr * STRA + 2 * qc;
        const float* bp = w_s + qc * STRW + qr * 16 + 4 * eb;

        #pragma unroll
        for (int k0 = 0; k0 < DD; k0 += 8) {
            const float2 A0 = *reinterpret_cast<const float2*>(ar + k0);
            const float2 A1 = *reinterpret_cast<const float2*>(ar + 8 * STRA + k0);
            const float2 A2 = *reinterpret_cast<const float2*>(ar + 16 * STRA + k0);
            const float2 A3 = *reinterpret_cast<const float2*>(ar + 24 * STRA + k0);
            const float* bk = bp + k0 * STRW;
            const float4 B0 = *reinterpret_cast<const float4*>(bk);
            const float4 B1 = *reinterpret_cast<const float4*>(bk + 4 * STRW);
            mma_tf32(acc[0][0][0],acc[0][0][1],acc[0][0][2],acc[0][0][3], A0.x,A1.x,A0.y,A1.y, B0.x,B1.x);
            mma_tf32(acc[1][0][0],acc[1][0][1],acc[1][0][2],acc[1][0][3], A2.x,A3.x,A2.y,A3.y, B0.x,B1.x);
            mma_tf32(acc[0][1][0],acc[0][1][1],acc[0][1][2],acc[0][1][3], A0.x,A1.x,A0.y,A1.y, B0.y,B1.y);
            mma_tf32(acc[1][1][0],acc[1][1][1],acc[1][1][2],acc[1][1][3], A2.x,A3.x,A2.y,A3.y, B0.y,B1.y);
            mma_tf32(acc[0][2][0],acc[0][2][1],acc[0][2][2],acc[0][2][3], A0.x,A1.x,A0.y,A1.y, B0.z,B1.z);
            mma_tf32(acc[1][2][0],acc[1][2][1],acc[1][2][2],acc[1][2][3], A2.x,A3.x,A2.y,A3.y, B0.z,B1.z);
            mma_tf32(acc[0][3][0],acc[0][3][1],acc[0][3][2],acc[0][3][3], A0.x,A1.x,A0.y,A1.y, B0.w,B1.w);
            mma_tf32(acc[1][3][0],acc[1][3][1],acc[1][3][2],acc[1][3][3], A2.x,A3.x,A2.y,A3.y, B0.w,B1.w);
        }

        // ---- score partials: rows {qr,qr+8,16+qr,24+qr}, this warp's 32 cols ----
        {
            const float* selfb = self_g + cur * DD;
            float pr[4] = {0.f, 0.f, 0.f, 0.f};
            #pragma unroll
            for (int j = 0; j < 4; ++j) {
                const int e0 = 32 * eb + 8 * j + 2 * qc;
                const float2 sv = *reinterpret_cast<const float2*>(selfb + e0);
                const float2 qv = *reinterpret_cast<const float2*>(q_s + e0);
                #pragma unroll
                for (int T = 0; T < 2; ++T) {
                    float v;
                    v = sv.x * acc[T][j][0]; v = (v >= 0.f) ? v : LRELU_ALPHA * v;
                    pr[2*T]   = fmaf(v, qv.x, pr[2*T]);
                    v = sv.y * acc[T][j][1]; v = (v >= 0.f) ? v : LRELU_ALPHA * v;
                    pr[2*T]   = fmaf(v, qv.y, pr[2*T]);
                    v = sv.x * acc[T][j][2]; v = (v >= 0.f) ? v : LRELU_ALPHA * v;
                    pr[2*T+1] = fmaf(v, qv.x, pr[2*T+1]);
                    v = sv.y * acc[T][j][3]; v = (v >= 0.f) ? v : LRELU_ALPHA * v;
                    pr[2*T+1] = fmaf(v, qv.y, pr[2*T+1]);
                }
            }
            #pragma unroll
            for (int i = 0; i < 4; ++i) {
                pr[i] += __shfl_xor_sync(0xffffffffu, pr[i], 1);
                pr[i] += __shfl_xor_sync(0xffffffffu, pr[i], 2);
            }
            if (qc == 0) {
                scoreG[eb * NNB + qr]      = pr[0];
                scoreG[eb * NNB + qr + 8]  = pr[1];
                scoreG[eb * NNB + qr + 16] = pr[2];
                scoreG[eb * NNB + qr + 24] = pr[3];
            }
        }
        barg(bid);                          // bar1: scores visible; nb[cur] dead

        issue_tile(p + 2 * stride, cur);    // refill freed buffer early

        // ---- softmax over 32 neighbors (warp 0 of group) ----
        if (eb == 0) {
            const float s = scoreG[lane] + scoreG[NNB + lane]
                          + scoreG[2 * NNB + lane] + scoreG[3 * NNB + lane];
            float mx = s;
            #pragma unroll
            for (int off = 16; off > 0; off >>= 1)
                mx = fmaxf(mx, __shfl_xor_sync(0xffffffffu, mx, off));
            const float ex = __expf(s - mx);
            float sum = ex;
            #pragma unroll
            for (int off = 16; off > 0; off >>= 1)
                sum += __shfl_xor_sync(0xffffffffu, sum, off);
            alpha_g[lane] = ex / sum;
        }

        cp_wait1();                         // next tile landed (own-thread view)
        barg(bid);                          // bar2: alpha + next tile visible

        // ---- register epilogue: out[e] = sum_n alpha[n]*msg (direct STG) ----
        {
            const float al0 = alpha_g[qr];
            const float al1 = alpha_g[qr + 8];
            const float al2 = alpha_g[qr + 16];
            const float al3 = alpha_g[qr + 24];
            float val[4][2];
            #pragma unroll
            for (int j = 0; j < 4; ++j)
                #pragma unroll
                for (int u = 0; u < 2; ++u) {
                    float v = al0 * acc[0][j][u];
                    v = fmaf(al1, acc[0][j][2 + u], v);
                    v = fmaf(al2, acc[1][j][u], v);
                    v = fmaf(al3, acc[1][j][2 + u], v);
                    v += __shfl_xor_sync(0xffffffffu, v, 4);
                    v += __shfl_xor_sync(0xffffffffu, v, 8);
                    v += __shfl_xor_sync(0xffffffffu, v, 16);
                    val[j][u] = v;
                }
            if (qr == 0) {
                float* op = out + (size_t)p * DD + 32 * eb + 2 * qc;
                #pragma unroll
                for (int j = 0; j < 4; ++j) {
                    op[8 * j]     = val[j][0];
                    op[8 * j + 1] = val[j][1];
                }
            }
        }
        // next iteration's bar1 orders alpha/score reuse; epilogue is register-only
    }
}

extern "C" void kernel_launch(void* const* d_in, const int* in_sizes, int n_in,
                              void* d_out, int out_size)
{
    const float* self_v = (const float*)d_in[0];   // [B,128]
    const float* nbv    = (const float*)d_in[1];   // [B,32,128]
    const float* w      = (const float*)d_in[2];   // [128,128]
    const float* q      = (const float*)d_in[3];   // [128,1]
    float*       out    = (float*)d_out;           // [B,128]

    const int B = in_sizes[0] / DD;                // 20000

    int smc = 0;
    cudaDeviceGetAttribute(&smc, cudaDevAttrMultiProcessorCount, 0);
    if (smc <= 0) smc = 148;
    int grid = smc;
    if (grid * NGRP > B) grid = (B + NGRP - 1) / NGRP;

    const size_t smem_bytes =
        (size_t)(DD * STRW + NGRP * 2 * NNB * STRA + NGRP * 2 * DD + DD
                 + NGRP * 4 * NNB + NGRP * NNB) * sizeof(float);   // 214,528 B

    cudaFuncSetAttribute(gat_grp, cudaFuncAttributeMaxDynamicSharedMemorySize,
                         (int)smem_bytes);

    gat_grp<<<grid, 512, smem_bytes>>>(self_v, nbv, w, q, out, B);
}

// round 9
// speedup vs baseline: 1.8067x; 1.4142x over previous
#include <cuda_runtime.h>
#include <cuda_fp16.h>
#include <cstdint>

#define DD    128
#define NNB   32
#define STRA  136              // nb_s fp32 stride (8 mod 32 -> conflict-free LDS.64 A)
#define WSTR  132              // w_h stride in u32 (half2) units; 528 B/row
#define NGRP  4
#define LRELU_ALPHA 0.2f

// w_h : k-pair row kp (=d/2), element = half2( w[2kp][e], w[2kp+1][e] )
//       within row: pos(e) = (e&7)*16 + (e>>3)  (u32 units) -> LDS.128 gives the
//       4 n-block B-fragments of one k-pair in one load, conflict-free.

__device__ __forceinline__ uint32_t pk_h2(float lo, float hi) {
    __half2 h = __floats2half2_rn(lo, hi);     // .x = lo half (bits [15:0])
    return *reinterpret_cast<uint32_t*>(&h);
}

__device__ __forceinline__ void mma_f16(float& c0, float& c1, float& c2, float& c3,
                                        uint32_t a0, uint32_t a1, uint32_t a2, uint32_t a3,
                                        uint32_t b0, uint32_t b1) {
    asm volatile(
        "mma.sync.aligned.m16n8k16.row.col.f32.f16.f16.f32 "
        "{%0,%1,%2,%3}, {%4,%5,%6,%7}, {%8,%9}, {%0,%1,%2,%3};"
        : "+f"(c0), "+f"(c1), "+f"(c2), "+f"(c3)
        : "r"(a0), "r"(a1), "r"(a2), "r"(a3), "r"(b0), "r"(b1));
}

__device__ __forceinline__ void cp_async16(uint32_t smem_addr, const void* gptr) {
    asm volatile("cp.async.cg.shared.global [%0], [%1], 16;\n"
                 :: "r"(smem_addr), "l"(gptr));
}
__device__ __forceinline__ void cp_commit() { asm volatile("cp.async.commit_group;\n" ::); }
__device__ __forceinline__ void cp_wait1()  { asm volatile("cp.async.wait_group 1;\n" ::); }

__device__ __forceinline__ void barg(int id) {
    asm volatile("bar.sync %0, 128;" :: "r"(id) : "memory");
}

extern "C" __global__ void __launch_bounds__(512, 1)
gat_h16(const float* __restrict__ self_v,
        const float* __restrict__ nbv,
        const float* __restrict__ w,
        const float* __restrict__ q,
        float* __restrict__ out,
        int B)
{
    extern __shared__ float sm[];
    uint32_t* w_h  = reinterpret_cast<uint32_t*>(sm);  // 64*132 = 8448 u32
    float* nb_s    = sm + 64 * WSTR;                   // 4*2*32*136 = 34816 f
    float* self_s  = nb_s + NGRP * 2 * NNB * STRA;     // 1024 f
    float* q_s     = self_s + NGRP * 2 * DD;           // 128 f
    float* scoreP  = q_s + DD;                         // 512 f
    float* alpha_s = scoreP + NGRP * 4 * NNB;          // 128 f

    const int t    = threadIdx.x;
    const int lane = t & 31;
    const int ww   = t >> 5;
    const int g    = ww >> 2;
    const int eb   = ww & 3;
    const int gt   = t & 127;
    const int qr   = lane >> 2;
    const int qc   = lane & 3;

    float* nb_g    = nb_s + g * 2 * NNB * STRA;
    float* self_g  = self_s + g * 2 * DD;
    float* scoreG  = scoreP + g * 4 * NNB;
    float* alpha_g = alpha_s + g * NNB;
    const int bid  = g + 1;

    // ---- one-time: w -> fp16 k-pair rows, fragment-major (RN rounding) ----
    {
        #pragma unroll
        for (int i = 0; i < 16; ++i) {                 // 8192 half2 / 512 thr
            const int fi = t + i * 512;
            const int kp = fi >> 7, e = fi & 127;
            const float wlo = w[(2 * kp) * DD + e];
            const float whi = w[(2 * kp + 1) * DD + e];
            w_h[kp * WSTR + (e & 7) * 16 + (e >> 3)] = pk_h2(wlo, whi);
        }
        if (t < DD) q_s[t] = q[t];
    }

    const int stride = gridDim.x * NGRP;
    const int p0     = blockIdx.x * NGRP + g;

    auto issue_tile = [&](int p, int buf) {
        if (p < B) {
            const float4* src = reinterpret_cast<const float4*>(nbv + (size_t)p * NNB * DD);
            const uint32_t dst0 =
                (uint32_t)__cvta_generic_to_shared(nb_g + buf * NNB * STRA);
            #pragma unroll
            for (int i = 0; i < 8; ++i) {              // 1024 float4 / 128 thr
                const int fi = gt + i * 128;
                const int r  = fi >> 5, c4 = fi & 31;
                cp_async16(dst0 + (uint32_t)(r * STRA + 4 * c4) * 4u, src + fi);
            }
            if (gt < 32) {
                const uint32_t ds =
                    (uint32_t)__cvta_generic_to_shared(self_g + buf * DD) + gt * 16u;
                cp_async16(ds, reinterpret_cast<const float4*>(self_v + (size_t)p * DD) + gt);
            }
        }
        cp_commit();
    };

    issue_tile(p0, 0);
    issue_tile(p0 + stride, 1);
    cp_wait1();
    __syncthreads();                // w_h + tile-0 cross-thread visibility (once)

    int it = 0;
    for (int p = p0; p < B; p += stride, ++it) {
        const int cur = it & 1;
        const float* nbuf = nb_g + cur * NNB * STRA;

        // ---- fp16 MMA mainloop: warp tile = 32 rows x 32 cols, k-chunk = 16 ----
        float acc[2][4][4];
        #pragma unroll
        for (int T = 0; T < 2; ++T)
            #pragma unroll
            for (int j = 0; j < 4; ++j)
                #pragma unroll
                for (int k = 0; k < 4; ++k) acc[T][j][k] = 0.f;

        const float* ar = nbuf + qr * STRA + 2 * qc;
        const uint32_t* wp = w_h + qc * WSTR + qr * 16 + 4 * eb;

        #pragma unroll
        for (int k0 = 0; k0 < DD; k0 += 16) {
            // A: rows {qr, qr+8, 16+qr, 24+qr}, k-pairs (k0+2qc, k0+2qc+8)
            const float2 A0a = *reinterpret_cast<const float2*>(ar + k0);
            const float2 A0b = *reinterpret_cast<const float2*>(ar + k0 + 8);
            const float2 A1a = *reinterpret_cast<const float2*>(ar + 8 * STRA + k0);
            const float2 A1b = *reinterpret_cast<const float2*>(ar + 8 * STRA + k0 + 8);
            const float2 A2a = *reinterpret_cast<const float2*>(ar + 16 * STRA + k0);
            const float2 A2b = *reinterpret_cast<const float2*>(ar + 16 * STRA + k0 + 8);
            const float2 A3a = *reinterpret_cast<const float2*>(ar + 24 * STRA + k0);
            const float2 A3b = *reinterpret_cast<const float2*>(ar + 24 * STRA + k0 + 8);

            const uint32_t a0T0 = pk_h2(A0a.x, A0a.y);   // (row qr,    k0+2qc..+1)
            const uint32_t a1T0 = pk_h2(A1a.x, A1a.y);   // (row qr+8)
            const uint32_t a2T0 = pk_h2(A0b.x, A0b.y);   // (row qr,    k0+2qc+8..+9)
            const uint32_t a3T0 = pk_h2(A1b.x, A1b.y);
            const uint32_t a0T1 = pk_h2(A2a.x, A2a.y);   // rows 16+qr / 24+qr
            const uint32_t a1T1 = pk_h2(A3a.x, A3a.y);
            const uint32_t a2T1 = pk_h2(A2b.x, A2b.y);
            const uint32_t a3T1 = pk_h2(A3b.x, A3b.y);

            // B: k-pair rows kp0+qc and kp0+qc+4 (folded qc into wp base)
            const int kp0 = k0 >> 1;
            const uint4 B0 = *reinterpret_cast<const uint4*>(wp + kp0 * WSTR);
            const uint4 B1 = *reinterpret_cast<const uint4*>(wp + (kp0 + 4) * WSTR);

            mma_f16(acc[0][0][0],acc[0][0][1],acc[0][0][2],acc[0][0][3], a0T0,a1T0,a2T0,a3T0, B0.x,B1.x);
            mma_f16(acc[1][0][0],acc[1][0][1],acc[1][0][2],acc[1][0][3], a0T1,a1T1,a2T1,a3T1, B0.x,B1.x);
            mma_f16(acc[0][1][0],acc[0][1][1],acc[0][1][2],acc[0][1][3], a0T0,a1T0,a2T0,a3T0, B0.y,B1.y);
            mma_f16(acc[1][1][0],acc[1][1][1],acc[1][1][2],acc[1][1][3], a0T1,a1T1,a2T1,a3T1, B0.y,B1.y);
            mma_f16(acc[0][2][0],acc[0][2][1],acc[0][2][2],acc[0][2][3], a0T0,a1T0,a2T0,a3T0, B0.z,B1.z);
            mma_f16(acc[1][2][0],acc[1][2][1],acc[1][2][2],acc[1][2][3], a0T1,a1T1,a2T1,a3T1, B0.z,B1.z);
            mma_f16(acc[0][3][0],acc[0][3][1],acc[0][3][2],acc[0][3][3], a0T0,a1T0,a2T0,a3T0, B0.w,B1.w);
            mma_f16(acc[1][3][0],acc[1][3][1],acc[1][3][2],acc[1][3][3], a0T1,a1T1,a2T1,a3T1, B0.w,B1.w);
        }

        // ---- score partials: rows {qr,qr+8,16+qr,24+qr}, this warp's 32 cols ----
        {
            const float* selfb = self_g + cur * DD;
            float pr[4] = {0.f, 0.f, 0.f, 0.f};
            #pragma unroll
            for (int j = 0; j < 4; ++j) {
                const int e0 = 32 * eb + 8 * j + 2 * qc;
                const float2 sv = *reinterpret_cast<const float2*>(selfb + e0);
                const float2 qv = *reinterpret_cast<const float2*>(q_s + e0);
                #pragma unroll
                for (int T = 0; T < 2; ++T) {
                    float v;
                    v = sv.x * acc[T][j][0]; v = (v >= 0.f) ? v : LRELU_ALPHA * v;
                    pr[2*T]   = fmaf(v, qv.x, pr[2*T]);
                    v = sv.y * acc[T][j][1]; v = (v >= 0.f) ? v : LRELU_ALPHA * v;
                    pr[2*T]   = fmaf(v, qv.y, pr[2*T]);
                    v = sv.x * acc[T][j][2]; v = (v >= 0.f) ? v : LRELU_ALPHA * v;
                    pr[2*T+1] = fmaf(v, qv.x, pr[2*T+1]);
                    v = sv.y * acc[T][j][3]; v = (v >= 0.f) ? v : LRELU_ALPHA * v;
                    pr[2*T+1] = fmaf(v, qv.y, pr[2*T+1]);
                }
            }
            #pragma unroll
            for (int i = 0; i < 4; ++i) {
                pr[i] += __shfl_xor_sync(0xffffffffu, pr[i], 1);
                pr[i] += __shfl_xor_sync(0xffffffffu, pr[i], 2);
            }
            if (qc == 0) {
                scoreG[eb * NNB + qr]      = pr[0];
                scoreG[eb * NNB + qr + 8]  = pr[1];
                scoreG[eb * NNB + qr + 16] = pr[2];
                scoreG[eb * NNB + qr + 24] = pr[3];
            }
        }
        barg(bid);                          // scores visible; nb[cur] dead

        issue_tile(p + 2 * stride, cur);    // refill freed buffer early

        // ---- softmax over 32 neighbors (warp 0 of group) ----
        if (eb == 0) {
            const float s = scoreG[lane] + scoreG[NNB + lane]
                          + scoreG[2 * NNB + lane] + scoreG[3 * NNB + lane];
            float mx = s;
            #pragma unroll
            for (int off = 16; off > 0; off >>= 1)
                mx = fmaxf(mx, __shfl_xor_sync(0xffffffffu, mx, off));
            const float ex = __expf(s - mx);
            float sum = ex;
            #pragma unroll
            for (int off = 16; off > 0; off >>= 1)
                sum += __shfl_xor_sync(0xffffffffu, sum, off);
            alpha_g[lane] = ex / sum;
        }

        cp_wait1();
        barg(bid);                          // alpha + next tile visible

        // ---- register epilogue: out[e] = sum_n alpha[n]*msg (direct STG) ----
        {
            const float al0 = alpha_g[qr];
            const float al1 = alpha_g[qr + 8];
            const float al2 = alpha_g[qr + 16];
            const float al3 = alpha_g[qr + 24];
            float val[4][2];
            #pragma unroll
            for (int j = 0; j < 4; ++j)
                #pragma unroll
                for (int u = 0; u < 2; ++u) {
                    float v = al0 * acc[0][j][u];
                    v = fmaf(al1, acc[0][j][2 + u], v);
                    v = fmaf(al2, acc[1][j][u], v);
                    v = fmaf(al3, acc[1][j][2 + u], v);
                    v += __shfl_xor_sync(0xffffffffu, v, 4);
                    v += __shfl_xor_sync(0xffffffffu, v, 8);
                    v += __shfl_xor_sync(0xffffffffu, v, 16);
                    val[j][u] = v;
                }
            if (qr == 0) {
                float* op = out + (size_t)p * DD + 32 * eb + 2 * qc;
                #pragma unroll
                for (int j = 0; j < 4; ++j) {
                    op[8 * j]     = val[j][0];
                    op[8 * j + 1] = val[j][1];
                }
            }
        }
    }
}

extern "C" void kernel_launch(void* const* d_in, const int* in_sizes, int n_in,
                              void* d_out, int out_size)
{
    const float* self_v = (const float*)d_in[0];   // [B,128]
    const float* nbv    = (const float*)d_in[1];   // [B,32,128]
    const float* w      = (const float*)d_in[2];   // [128,128]
    const float* q      = (const float*)d_in[3];   // [128,1]
    float*       out    = (float*)d_out;           // [B,128]

    const int B = in_sizes[0] / DD;                // 20000

    int smc = 0;
    cudaDeviceGetAttribute(&smc, cudaDevAttrMultiProcessorCount, 0);
    if (smc <= 0) smc = 148;
    int grid = smc;
    if (grid * NGRP > B) grid = (B + NGRP - 1) / NGRP;

    const size_t smem_bytes =
        (size_t)(64 * WSTR + NGRP * 2 * NNB * STRA + NGRP * 2 * DD + DD
                 + NGRP * 4 * NNB + NGRP * NNB) * sizeof(float);   // ~180 KB

    cudaFuncSetAttribute(gat_h16, cudaFuncAttributeMaxDynamicSharedMemorySize,
                         (int)smem_bytes);

    gat_h16<<<grid, 512, smem_bytes>>>(self_v, nbv, w, q, out, B);
}